// round 9
// baseline (speedup 1.0000x reference)
#include <cuda_runtime.h>
#include <cuda_bf16.h>
#include <stdint.h>

#define B_   4
#define C_   256
#define CI_  128
#define N_   4096
#define NCH  64                 // 64 j-chunks of 64

// ---------------- scratch (allocation-free rule) ----------------
__device__ __nv_bfloat16 d_gT[B_*N_*CI_];   // [b][j][ci]  (V transposed)
__device__ __nv_bfloat16 d_tT[B_*N_*CI_];   // [b][n][ci]  (Q)
__device__ __nv_bfloat16 d_pT[B_*N_*CI_];   // [b][n][ci]  (K)
__device__ __nv_bfloat16 d_yT[B_*N_*CI_];   // [b][n][ci]

// ---------------- helpers ----------------
__device__ __forceinline__ uint32_t smem_u32(const void* p) {
    uint32_t a;
    asm("{ .reg .u64 t; cvta.to.shared.u64 t, %1; cvt.u32.u64 %0, t; }"
        : "=r"(a) : "l"(p));
    return a;
}
__device__ __forceinline__ void ldsm_x4(uint32_t addr, uint32_t& r0, uint32_t& r1,
                                        uint32_t& r2, uint32_t& r3) {
    asm volatile("ldmatrix.sync.aligned.m8n8.x4.shared.b16 {%0,%1,%2,%3}, [%4];"
                 : "=r"(r0), "=r"(r1), "=r"(r2), "=r"(r3) : "r"(addr));
}
__device__ __forceinline__ void ldsm_x4_t(uint32_t addr, uint32_t& r0, uint32_t& r1,
                                          uint32_t& r2, uint32_t& r3) {
    asm volatile("ldmatrix.sync.aligned.m8n8.x4.trans.shared.b16 {%0,%1,%2,%3}, [%4];"
                 : "=r"(r0), "=r"(r1), "=r"(r2), "=r"(r3) : "r"(addr));
}
__device__ __forceinline__ void mma_bf16(float* c, const uint32_t* a,
                                         uint32_t b0, uint32_t b1) {
    asm volatile(
        "mma.sync.aligned.m16n8k16.row.col.f32.bf16.bf16.f32 "
        "{%0,%1,%2,%3}, {%4,%5,%6,%7}, {%8,%9}, {%0,%1,%2,%3};"
        : "+f"(c[0]), "+f"(c[1]), "+f"(c[2]), "+f"(c[3])
        : "r"(a[0]), "r"(a[1]), "r"(a[2]), "r"(a[3]), "r"(b0), "r"(b1));
}
__device__ __forceinline__ uint32_t pack_bf16(float lo, float hi) {
    uint32_t r;
    asm("cvt.rn.bf16x2.f32 %0, %1, %2;" : "=r"(r) : "f"(hi), "f"(lo));
    return r;
}
__device__ __forceinline__ void cp_async16(uint32_t d, const void* s) {
    asm volatile("cp.async.cg.shared.global [%0], [%1], 16;"
                 :: "r"(d), "l"(s) : "memory");
}
__device__ __forceinline__ void cp_commit() {
    asm volatile("cp.async.commit_group;" ::: "memory");
}
__device__ __forceinline__ void cp_wait0() {
    asm volatile("cp.async.wait_group 0;" ::: "memory");
}

// ---------------------------------------------------------------------------
// proj_tc: per 128-n tile, C[n][ci] = sum_c x[c][n]*W[ci][c] + bias, for
// Wg -> d_gT, Wt -> d_tT, Wp -> d_pT.
// A = x^T via trans-ldmatrix (all 16 K-frags hoisted, reused for 3 weights);
// W chunks double-buffered with register-staged prefetch.
// ---------------------------------------------------------------------------
#define PX_OFF 0                   // x tile: 256 c-rows x 272B (128 n bf16 + pad)
#define PXROW  272
#define PW_OFF 69632               // W chunk buffers: 2 x (128 ci-rows x 144B)
#define PWROW  144
#define PWBUF  18432
#define P_SMEM 106496

__global__ __launch_bounds__(256, 1) void proj_tc_kernel(
    const float* __restrict__ x,
    const float* __restrict__ Wg, const float* __restrict__ bg,
    const float* __restrict__ Wt, const float* __restrict__ bt,
    const float* __restrict__ Wp, const float* __restrict__ bp)
{
    extern __shared__ char smem[];
    const uint32_t sb = smem_u32(smem);
    const int tid  = threadIdx.x;
    const int lane = tid & 31;
    const int wid  = tid >> 5;
    const int b    = blockIdx.y;
    const int n0   = blockIdx.x * 128;
    const int iw   = wid * 16;
    const int lr   = lane & 7;
    const int ls8  = (lane >> 3) * 8;

    const float* Warr[3] = {Wg, Wt, Wp};
    const float* barr[3] = {bg, bt, bp};
    __nv_bfloat16* darr[3] = {d_gT, d_tT, d_pT};

    // ---- load x tile [256 c][128 n] fp32 -> bf16 smem ----
    #pragma unroll
    for (int it = 0; it < 32; it++) {
        int g = tid + it * 256;            // 8192 granules of 4 floats
        int row = g >> 5, n4 = g & 31;
        float4 f = *(const float4*)&x[((size_t)b * C_ + row) * N_ + n0 + n4 * 4];
        uint2 u;
        u.x = pack_bf16(f.x, f.y);
        u.y = pack_bf16(f.z, f.w);
        *(uint2*)(smem + PX_OFF + row * PXROW + n4 * 8) = u;
    }
    // ---- W chunk 0 (w=0, kc=0) -> buffer 0 ----
    #pragma unroll
    for (int it = 0; it < 4; it++) {
        int g = tid + it * 256;            // 1024 granules of 8 elems
        int ci = g >> 3, c8 = g & 7;
        const float* ws = Wg + (size_t)ci * C_ + c8 * 8;
        float4 f0 = *(const float4*)ws;
        float4 f1 = *(const float4*)(ws + 4);
        uint4 u;
        u.x = pack_bf16(f0.x, f0.y);
        u.y = pack_bf16(f0.z, f0.w);
        u.z = pack_bf16(f1.x, f1.y);
        u.w = pack_bf16(f1.z, f1.w);
        *(uint4*)(smem + PW_OFF + ci * PWROW + c8 * 16) = u;
    }
    __syncthreads();

    // ---- hoist all 16 A-fragments (K=256) from x tile ----
    const int arow_k = ((lane >> 4) & 1) * 8 + (lane & 7);
    const int acol_m = iw + ((lane >> 3) & 1) * 8;
    uint32_t af[16][4];
    #pragma unroll
    for (int kt = 0; kt < 16; kt++) {
        uint32_t addr = sb + PX_OFF + (uint32_t)(kt * 16 + arow_k) * PXROW + acol_m * 2;
        ldsm_x4_t(addr, af[kt][0], af[kt][1], af[kt][2], af[kt][3]);
    }

    float cacc[16][4];
    const int row0 = n0 + iw + (lane >> 2);

    for (int step = 0; step < 12; step++) {
        const int w  = step >> 2;
        const int kc = step & 3;
        if (kc == 0) {
            #pragma unroll
            for (int ct = 0; ct < 16; ct++)
                #pragma unroll
                for (int q = 0; q < 4; q++) cacc[ct][q] = 0.f;
        }

        // stage next W chunk into regs
        float4 wst[8];
        const bool more = (step + 1 < 12);
        if (more) {
            const int w2  = (step + 1) >> 2;
            const int kc2 = (step + 1) & 3;
            const float* Wn = Warr[w2];
            #pragma unroll
            for (int it = 0; it < 4; it++) {
                int g = tid + it * 256;
                int ci = g >> 3, c8 = g & 7;
                const float* ws = Wn + (size_t)ci * C_ + kc2 * 64 + c8 * 8;
                wst[2 * it]     = *(const float4*)ws;
                wst[2 * it + 1] = *(const float4*)(ws + 4);
            }
        }

        // MMA from current buffer
        const uint32_t wb = sb + PW_OFF + (uint32_t)(step & 1) * PWBUF;
        #pragma unroll
        for (int ct = 0; ct < 16; ct++) {
            uint32_t rowaddr = wb + (ct * 8 + lr) * PWROW + ls8 * 2;
            #pragma unroll
            for (int kt2 = 0; kt2 < 2; kt2++) {
                uint32_t b0, b1, b2, b3;
                ldsm_x4(rowaddr + kt2 * 64, b0, b1, b2, b3);
                mma_bf16(cacc[ct], af[kc * 4 + 2 * kt2],     b0, b1);
                mma_bf16(cacc[ct], af[kc * 4 + 2 * kt2 + 1], b2, b3);
            }
        }

        // commit staged chunk to the other buffer
        if (more) {
            char* wdst = smem + PW_OFF + (size_t)((step + 1) & 1) * PWBUF;
            #pragma unroll
            for (int it = 0; it < 4; it++) {
                int g = tid + it * 256;
                int ci = g >> 3, c8 = g & 7;
                uint4 u;
                u.x = pack_bf16(wst[2*it].x,   wst[2*it].y);
                u.y = pack_bf16(wst[2*it].z,   wst[2*it].w);
                u.z = pack_bf16(wst[2*it+1].x, wst[2*it+1].y);
                u.w = pack_bf16(wst[2*it+1].z, wst[2*it+1].w);
                *(uint4*)(wdst + ci * PWROW + c8 * 16) = u;
            }
        }

        // epilogue after last K chunk of this weight
        if (kc == 3) {
            const float* bias = barr[w];
            __nv_bfloat16* dst = darr[w];
            #pragma unroll
            for (int ct = 0; ct < 16; ct++) {
                const int cidx = ct * 8 + 2 * (lane & 3);
                float bv0 = bias[cidx], bv1 = bias[cidx + 1];
                *(uint32_t*)&dst[((size_t)b * N_ + row0)     * CI_ + cidx] =
                    pack_bf16(cacc[ct][0] + bv0, cacc[ct][1] + bv1);
                *(uint32_t*)&dst[((size_t)b * N_ + row0 + 8) * CI_ + cidx] =
                    pack_bf16(cacc[ct][2] + bv0, cacc[ct][3] + bv1);
            }
        }
        __syncthreads();
    }
}

// ---------------------------------------------------------------------------
// mma.sync flash attention (no-rescale online softmax), cp.async K/V staging.
// ---------------------------------------------------------------------------
#define QS_OFF 0
#define QROW   272
#define KS_OFF 34816
#define KROWB  272
#define KBUF   17408               // 64 rows * 272
#define VS_OFF 69632
#define VROWT  272
#define VBUF   17408               // 64 rows * 272
#define SM_TOT 104448

__global__ __launch_bounds__(256, 1) void attn_mma_kernel()
{
    extern __shared__ char smem[];
    const uint32_t sb  = smem_u32(smem);
    const int tid  = threadIdx.x;
    const int lane = tid & 31;
    const int wid  = tid >> 5;
    const int b    = blockIdx.y;
    const int i0   = blockIdx.x * 128;
    const int iw   = wid * 16;

    const __nv_bfloat16* qg = d_tT + ((size_t)b * N_ + i0) * CI_;
    const __nv_bfloat16* kp = d_pT + (size_t)b * N_ * CI_;
    const __nv_bfloat16* gp = d_gT + (size_t)b * N_ * CI_;

    // ---- prologue via cp.async: Q (2048 granules), K0/V0 (1024 each) ----
    #pragma unroll
    for (int it = 0; it < 8; it++) {
        int g = tid + it * 256;
        int row = g >> 4, c8 = g & 15;
        cp_async16(sb + QS_OFF + row * QROW + c8 * 16,
                   qg + (size_t)row * CI_ + c8 * 8);
    }
    #pragma unroll
    for (int it = 0; it < 4; it++) {
        int g = tid + it * 256;
        int row = g >> 4, c8 = g & 15;
        cp_async16(sb + KS_OFF + row * KROWB + c8 * 16,
                   kp + (size_t)row * CI_ + c8 * 8);
        cp_async16(sb + VS_OFF + row * VROWT + c8 * 16,
                   gp + (size_t)row * CI_ + c8 * 8);
    }
    cp_commit();
    cp_wait0();
    __syncthreads();

    // ---- Q fragments, held in registers for the whole kernel ----
    uint32_t qf[8][4];
    {
        const int sub = lane >> 3, r = lane & 7;
        const int qrow = iw + (sub & 1) * 8 + r;
        const int qcol = (sub >> 1) * 8;
        #pragma unroll
        for (int kt = 0; kt < 8; kt++) {
            uint32_t addr = sb + QS_OFF + qrow * QROW + (kt * 16 + qcol) * 2;
            ldsm_x4(addr, qf[kt][0], qf[kt][1], qf[kt][2], qf[kt][3]);
        }
    }

    float yacc[16][4];
    #pragma unroll
    for (int ct = 0; ct < 16; ct++)
        #pragma unroll
        for (int q = 0; q < 4; q++) yacc[ct][q] = 0.f;
    float l0 = 0.f, l1 = 0.f;

    const int lr  = lane & 7;
    const int ls8 = (lane >> 3) * 8;

    for (int n = 0; n < NCH; n++) {
        // async-stage next chunk into the other buffers
        const bool more = (n + 1 < NCH);
        if (more) {
            const size_t jb = (size_t)(n + 1) * 64;
            const uint32_t kdst = sb + KS_OFF + (uint32_t)((n + 1) & 1) * KBUF;
            const uint32_t vdst = sb + VS_OFF + (uint32_t)((n + 1) & 1) * VBUF;
            #pragma unroll
            for (int it = 0; it < 4; it++) {
                int g = tid + it * 256;
                int row = g >> 4, c8 = g & 15;
                cp_async16(kdst + row * KROWB + c8 * 16,
                           kp + (jb + row) * CI_ + c8 * 8);
                cp_async16(vdst + row * VROWT + c8 * 16,
                           gp + (jb + row) * CI_ + c8 * 8);
            }
            cp_commit();
        }

        const uint32_t kb = sb + KS_OFF + (uint32_t)(n & 1) * KBUF;
        const uint32_t vb = sb + VS_OFF + (uint32_t)(n & 1) * VBUF;

        // ---- S = Q K^T  (128 x 64, K=128) ----
        float sacc[8][4];
        #pragma unroll
        for (int jt = 0; jt < 8; jt++)
            #pragma unroll
            for (int q = 0; q < 4; q++) sacc[jt][q] = 0.f;

        #pragma unroll
        for (int jt = 0; jt < 8; jt++) {
            uint32_t rowaddr = kb + (jt * 8 + lr) * KROWB + ls8 * 2;
            #pragma unroll
            for (int kt2 = 0; kt2 < 4; kt2++) {
                uint32_t b0, b1, b2, b3;
                ldsm_x4(rowaddr + kt2 * 64, b0, b1, b2, b3);
                mma_bf16(sacc[jt], qf[2 * kt2],     b0, b1);
                mma_bf16(sacc[jt], qf[2 * kt2 + 1], b2, b3);
            }
        }

        // ---- exp + row-sum; repack C frags as A frags for P·V ----
        uint32_t pa[4][4];
        #pragma unroll
        for (int st = 0; st < 8; st++) {
            float e0 = __expf(sacc[st][0]);
            float e1 = __expf(sacc[st][1]);
            float e2 = __expf(sacc[st][2]);
            float e3 = __expf(sacc[st][3]);
            l0 += e0 + e1;
            l1 += e2 + e3;
            pa[st >> 1][(st & 1) * 2 + 0] = pack_bf16(e0, e1);
            pa[st >> 1][(st & 1) * 2 + 1] = pack_bf16(e2, e3);
        }

        // ---- Y += P V^T, V^T via trans-ldmatrix from [j][c] chunk ----
        #pragma unroll
        for (int ct = 0; ct < 16; ct++) {
            uint32_t base = vb + ((lane >> 3) * 8 + (lane & 7)) * VROWT + ct * 16;
            #pragma unroll
            for (int j2 = 0; j2 < 2; j2++) {
                uint32_t b0, b1, b2, b3;
                ldsm_x4_t(base + j2 * 32 * VROWT, b0, b1, b2, b3);
                mma_bf16(yacc[ct], pa[2 * j2],     b0, b1);
                mma_bf16(yacc[ct], pa[2 * j2 + 1], b2, b3);
            }
        }

        if (more) cp_wait0();
        __syncthreads();
    }

    // ---- finalize: quad-reduce row sums, normalize, store bf16 ----
    l0 += __shfl_xor_sync(0xffffffffu, l0, 1);
    l0 += __shfl_xor_sync(0xffffffffu, l0, 2);
    l1 += __shfl_xor_sync(0xffffffffu, l1, 1);
    l1 += __shfl_xor_sync(0xffffffffu, l1, 2);
    const float r0 = 1.f / l0;
    const float r1 = 1.f / l1;

    const int row0 = i0 + iw + (lane >> 2);
    uint32_t* y0 = (uint32_t*)(d_yT + ((size_t)b * N_ + row0)     * CI_ + 2 * (lane & 3));
    uint32_t* y1 = (uint32_t*)(d_yT + ((size_t)b * N_ + row0 + 8) * CI_ + 2 * (lane & 3));
    #pragma unroll
    for (int ct = 0; ct < 16; ct++) {
        y0[ct * 4] = pack_bf16(yacc[ct][0] * r0, yacc[ct][1] * r0);
        y1[ct * 4] = pack_bf16(yacc[ct][2] * r1, yacc[ct][3] * r1);
    }
}

// ---------------------------------------------------------------------------
// out_tc: out[o][n] = sum_ci Wo[o][ci]*yT[n][ci] + bo[o] + x[o][n]
// A = Wo rows (preloaded frags), B = yT rows. Tile [128 o][128 n], K=128.
// Per-nt immediate store -> low regs -> 2 CTAs/SM.
// ---------------------------------------------------------------------------
#define OW_OFF 0                   // Wo tile: 128 o-rows x 272B
#define OWROW  272
#define OY_OFF 34816               // yT tile: 128 n-rows x 272B
#define OYROW  272
#define O_SMEM 69632

__global__ __launch_bounds__(256, 2) void out_tc_kernel(
    const float* __restrict__ x,
    const float* __restrict__ Wo, const float* __restrict__ bo,
    float* __restrict__ out)
{
    extern __shared__ char smem[];
    const uint32_t sb = smem_u32(smem);
    const int tid  = threadIdx.x;
    const int lane = tid & 31;
    const int wid  = tid >> 5;
    const int b    = blockIdx.z;
    const int o0   = blockIdx.y * 128;
    const int n0   = blockIdx.x * 128;
    const int iw   = wid * 16;
    const int lr   = lane & 7;
    const int ls8  = (lane >> 3) * 8;

    // yT tile via cp.async (raw bf16)
    #pragma unroll
    for (int it = 0; it < 8; it++) {
        int g = tid + it * 256;
        int row = g >> 4, c8 = g & 15;
        cp_async16(sb + OY_OFF + row * OYROW + c8 * 16,
                   d_yT + ((size_t)b * N_ + n0 + row) * CI_ + c8 * 8);
    }
    cp_commit();
    // Wo tile fp32 -> bf16 (needs conversion, regular loads)
    #pragma unroll
    for (int it = 0; it < 8; it++) {
        int g = tid + it * 256;
        int o = g >> 4, c8 = g & 15;
        const float* ws = Wo + (size_t)(o0 + o) * CI_ + c8 * 8;
        float4 f0 = *(const float4*)ws;
        float4 f1 = *(const float4*)(ws + 4);
        uint4 u;
        u.x = pack_bf16(f0.x, f0.y);
        u.y = pack_bf16(f0.z, f0.w);
        u.z = pack_bf16(f1.x, f1.y);
        u.w = pack_bf16(f1.z, f1.w);
        *(uint4*)(smem + OW_OFF + o * OWROW + c8 * 16) = u;
    }
    cp_wait0();
    __syncthreads();

    // A fragments (Wo, 16 o-rows per warp, K=128)
    uint32_t af[8][4];
    {
        const int sub = lane >> 3, r = lane & 7;
        const int arow = iw + (sub & 1) * 8 + r;
        const int acol = (sub >> 1) * 8;
        #pragma unroll
        for (int kt = 0; kt < 8; kt++) {
            uint32_t addr = sb + OW_OFF + arow * OWROW + (kt * 16 + acol) * 2;
            ldsm_x4(addr, af[kt][0], af[kt][1], af[kt][2], af[kt][3]);
        }
    }

    const int orow = o0 + iw + (lane >> 2);
    const float bv0 = bo[orow];
    const float bv1 = bo[orow + 8];

    #pragma unroll
    for (int nt = 0; nt < 16; nt++) {
        float acc[4] = {0.f, 0.f, 0.f, 0.f};
        uint32_t rowaddr = sb + OY_OFF + (nt * 8 + lr) * OYROW + ls8 * 2;
        #pragma unroll
        for (int kt2 = 0; kt2 < 4; kt2++) {
            uint32_t b0, b1, b2, b3;
            ldsm_x4(rowaddr + kt2 * 64, b0, b1, b2, b3);
            mma_bf16(acc, af[2 * kt2],     b0, b1);
            mma_bf16(acc, af[2 * kt2 + 1], b2, b3);
        }
        const int ncol = n0 + nt * 8 + 2 * (lane & 3);
        const size_t i0b = ((size_t)b * C_ + orow)     * N_ + ncol;
        const size_t i1b = ((size_t)b * C_ + orow + 8) * N_ + ncol;
        float2 xr0 = *(const float2*)&x[i0b];
        float2 xr1 = *(const float2*)&x[i1b];
        *(float2*)&out[i0b] = make_float2(acc[0] + bv0 + xr0.x,
                                          acc[1] + bv0 + xr0.y);
        *(float2*)&out[i1b] = make_float2(acc[2] + bv1 + xr1.x,
                                          acc[3] + bv1 + xr1.y);
    }
}

// ---------------------------------------------------------------------------
extern "C" void kernel_launch(void* const* d_in, const int* in_sizes, int n_in,
                              void* d_out, int out_size)
{
    const float* x  = (const float*)d_in[0];
    const float* Wg = (const float*)d_in[1];
    const float* bg = (const float*)d_in[2];
    const float* Wt = (const float*)d_in[3];
    const float* bt = (const float*)d_in[4];
    const float* Wp = (const float*)d_in[5];
    const float* bp = (const float*)d_in[6];
    const float* Wo = (const float*)d_in[7];
    const float* bo = (const float*)d_in[8];
    float* out = (float*)d_out;

    cudaFuncSetAttribute(proj_tc_kernel,
                         cudaFuncAttributeMaxDynamicSharedMemorySize, P_SMEM);
    cudaFuncSetAttribute(attn_mma_kernel,
                         cudaFuncAttributeMaxDynamicSharedMemorySize, SM_TOT);
    cudaFuncSetAttribute(out_tc_kernel,
                         cudaFuncAttributeMaxDynamicSharedMemorySize, O_SMEM);

    proj_tc_kernel<<<dim3(N_ / 128, B_), 256, P_SMEM>>>(x, Wg, bg, Wt, bt, Wp, bp);
    attn_mma_kernel<<<dim3(N_ / 128, B_), 256, SM_TOT>>>();
    out_tc_kernel<<<dim3(N_ / 128, 2, B_), 256, O_SMEM>>>(x, Wo, bo, out);
}

// round 10
// speedup vs baseline: 1.0424x; 1.0424x over previous
#include <cuda_runtime.h>
#include <cuda_bf16.h>
#include <stdint.h>

#define B_   4
#define C_   256
#define CI_  128
#define N_   4096
#define NCH  64                 // 64 j-chunks of 64
#define WSZ  (CI_*C_)           // 32768

// ---------------- scratch (allocation-free rule) ----------------
__device__ __nv_bfloat16 d_gT[B_*N_*CI_];   // [b][j][ci]  (V transposed)
__device__ __nv_bfloat16 d_tT[B_*N_*CI_];   // [b][n][ci]  (Q)
__device__ __nv_bfloat16 d_pT[B_*N_*CI_];   // [b][n][ci]  (K)
__device__ __nv_bfloat16 d_yT[B_*N_*CI_];   // [b][n][ci]
__device__ __nv_bfloat16 d_Wb[3*WSZ];       // bf16 Wg/Wt/Wp [w][ci][c]
__device__ __nv_bfloat16 d_Wob[WSZ];        // bf16 Wo [o][ci]

// ---------------- helpers ----------------
__device__ __forceinline__ uint32_t smem_u32(const void* p) {
    uint32_t a;
    asm("{ .reg .u64 t; cvta.to.shared.u64 t, %1; cvt.u32.u64 %0, t; }"
        : "=r"(a) : "l"(p));
    return a;
}
__device__ __forceinline__ void ldsm_x4(uint32_t addr, uint32_t& r0, uint32_t& r1,
                                        uint32_t& r2, uint32_t& r3) {
    asm volatile("ldmatrix.sync.aligned.m8n8.x4.shared.b16 {%0,%1,%2,%3}, [%4];"
                 : "=r"(r0), "=r"(r1), "=r"(r2), "=r"(r3) : "r"(addr));
}
__device__ __forceinline__ void ldsm_x4_t(uint32_t addr, uint32_t& r0, uint32_t& r1,
                                          uint32_t& r2, uint32_t& r3) {
    asm volatile("ldmatrix.sync.aligned.m8n8.x4.trans.shared.b16 {%0,%1,%2,%3}, [%4];"
                 : "=r"(r0), "=r"(r1), "=r"(r2), "=r"(r3) : "r"(addr));
}
__device__ __forceinline__ void mma_bf16(float* c, const uint32_t* a,
                                         uint32_t b0, uint32_t b1) {
    asm volatile(
        "mma.sync.aligned.m16n8k16.row.col.f32.bf16.bf16.f32 "
        "{%0,%1,%2,%3}, {%4,%5,%6,%7}, {%8,%9}, {%0,%1,%2,%3};"
        : "+f"(c[0]), "+f"(c[1]), "+f"(c[2]), "+f"(c[3])
        : "r"(a[0]), "r"(a[1]), "r"(a[2]), "r"(a[3]), "r"(b0), "r"(b1));
}
__device__ __forceinline__ uint32_t pack_bf16(float lo, float hi) {
    uint32_t r;
    asm("cvt.rn.bf16x2.f32 %0, %1, %2;" : "=r"(r) : "f"(hi), "f"(lo));
    return r;
}
__device__ __forceinline__ void cp_async16(uint32_t d, const void* s) {
    asm volatile("cp.async.cg.shared.global [%0], [%1], 16;"
                 :: "r"(d), "l"(s) : "memory");
}
__device__ __forceinline__ void cp_commit() {
    asm volatile("cp.async.commit_group;" ::: "memory");
}
__device__ __forceinline__ void cp_wait0() {
    asm volatile("cp.async.wait_group 0;" ::: "memory");
}

// ---------------------------------------------------------------------------
// wconv: one-time fp32 -> bf16 weight conversion
// ---------------------------------------------------------------------------
__global__ __launch_bounds__(256) void wconv_kernel(
    const float* __restrict__ Wg, const float* __restrict__ Wt,
    const float* __restrict__ Wp, const float* __restrict__ Wo)
{
    const int idx = (blockIdx.x * 256 + threadIdx.x) * 4;
    if (idx < 3 * WSZ) {
        const int w = idx / WSZ, off = idx - w * WSZ;
        const float* W = (w == 0) ? Wg : (w == 1 ? Wt : Wp);
        float4 f = *(const float4*)&W[off];
        uint2 u;
        u.x = pack_bf16(f.x, f.y);
        u.y = pack_bf16(f.z, f.w);
        *(uint2*)&d_Wb[idx] = u;
    }
    if (idx < WSZ) {
        float4 f = *(const float4*)&Wo[idx];
        uint2 u;
        u.x = pack_bf16(f.x, f.y);
        u.y = pack_bf16(f.z, f.w);
        *(uint2*)&d_Wob[idx] = u;
    }
}

// ---------------------------------------------------------------------------
// proj_tc: 64-n tiles, 2 CTAs/SM. C[n][ci] = sum_c x[c][n]*W[ci][c] + bias.
// Warp (mw = wid&3) covers 16 n-rows; (h = wid>>2) covers 64 of 128 ci.
// W chunks (bf16) double-buffered via cp.async.
// ---------------------------------------------------------------------------
#define PX_OFF 0                   // x tile: 256 c-rows x 144B (64 n bf16 + pad)
#define PXROW  144
#define PW_OFF 36864               // W bufs: 2 x (128 ci-rows x 144B)
#define PWROW  144
#define PWBUF  18432
#define P_SMEM 73728

__global__ __launch_bounds__(256, 2) void proj_tc_kernel(
    const float* __restrict__ x,
    const float* __restrict__ bg, const float* __restrict__ bt,
    const float* __restrict__ bp)
{
    extern __shared__ char smem[];
    const uint32_t sb = smem_u32(smem);
    const int tid  = threadIdx.x;
    const int lane = tid & 31;
    const int wid  = tid >> 5;
    const int b    = blockIdx.y;
    const int n0   = blockIdx.x * 64;
    const int mw   = wid & 3;
    const int h    = wid >> 2;
    const int lr   = lane & 7;
    const int ls8  = (lane >> 3) * 8;

    const float* barr[3] = {bg, bt, bp};
    __nv_bfloat16* darr[3] = {d_gT, d_tT, d_pT};

    // ---- W chunk 0 (w=0, kc=0) via cp.async ----
    #pragma unroll
    for (int it = 0; it < 4; it++) {
        int g = tid + it * 256;            // 1024 granules
        int ci = g >> 3, c8 = g & 7;
        cp_async16(sb + PW_OFF + ci * PWROW + c8 * 16,
                   d_Wb + (size_t)ci * C_ + c8 * 8);
    }
    cp_commit();
    // ---- x tile [256 c][64 n] fp32 -> bf16 smem ----
    #pragma unroll
    for (int it = 0; it < 16; it++) {
        int g = tid + it * 256;            // 4096 granules of 4 floats
        int row = g >> 4, n4 = g & 15;
        float4 f = *(const float4*)&x[((size_t)b * C_ + row) * N_ + n0 + n4 * 4];
        uint2 u;
        u.x = pack_bf16(f.x, f.y);
        u.y = pack_bf16(f.z, f.w);
        *(uint2*)(smem + PX_OFF + row * PXROW + n4 * 8) = u;
    }
    cp_wait0();
    __syncthreads();

    const int arow_k = ((lane >> 4) & 1) * 8 + (lane & 7);
    const int acol_m = mw * 16 + ((lane >> 3) & 1) * 8;
    const int row0   = n0 + mw * 16 + (lane >> 2);

    float cacc[8][4];

    for (int step = 0; step < 12; step++) {
        const int w  = step >> 2;
        const int kc = step & 3;
        if (kc == 0) {
            #pragma unroll
            for (int ct = 0; ct < 8; ct++)
                #pragma unroll
                for (int q = 0; q < 4; q++) cacc[ct][q] = 0.f;
        }

        const bool more = (step + 1 < 12);
        if (more) {
            const int w2  = (step + 1) >> 2;
            const int kc2 = (step + 1) & 3;
            const __nv_bfloat16* Wn = d_Wb + (size_t)w2 * WSZ + kc2 * 64;
            const uint32_t wd = sb + PW_OFF + (uint32_t)((step + 1) & 1) * PWBUF;
            #pragma unroll
            for (int it = 0; it < 4; it++) {
                int g = tid + it * 256;
                int ci = g >> 3, c8 = g & 7;
                cp_async16(wd + ci * PWROW + c8 * 16,
                           Wn + (size_t)ci * C_ + c8 * 8);
            }
            cp_commit();
        }

        // A frags for this kc (trans from x tile)
        uint32_t af[4][4];
        #pragma unroll
        for (int kt = 0; kt < 4; kt++) {
            uint32_t addr = sb + PX_OFF +
                (uint32_t)(kc * 64 + kt * 16 + arow_k) * PXROW + acol_m * 2;
            ldsm_x4_t(addr, af[kt][0], af[kt][1], af[kt][2], af[kt][3]);
        }

        // B frags from current W buffer + MMA (warp's 64-ci half)
        const uint32_t wb = sb + PW_OFF + (uint32_t)(step & 1) * PWBUF;
        #pragma unroll
        for (int ct = 0; ct < 8; ct++) {
            uint32_t rowaddr = wb + (h * 64 + ct * 8 + lr) * PWROW + ls8 * 2;
            #pragma unroll
            for (int kt2 = 0; kt2 < 2; kt2++) {
                uint32_t b0, b1, b2, b3;
                ldsm_x4(rowaddr + kt2 * 64, b0, b1, b2, b3);
                mma_bf16(cacc[ct], af[2 * kt2],     b0, b1);
                mma_bf16(cacc[ct], af[2 * kt2 + 1], b2, b3);
            }
        }

        if (kc == 3) {
            const float* bias = barr[w];
            __nv_bfloat16* dst = darr[w];
            #pragma unroll
            for (int ct = 0; ct < 8; ct++) {
                const int cidx = h * 64 + ct * 8 + 2 * (lane & 3);
                float bv0 = bias[cidx], bv1 = bias[cidx + 1];
                *(uint32_t*)&dst[((size_t)b * N_ + row0)     * CI_ + cidx] =
                    pack_bf16(cacc[ct][0] + bv0, cacc[ct][1] + bv1);
                *(uint32_t*)&dst[((size_t)b * N_ + row0 + 8) * CI_ + cidx] =
                    pack_bf16(cacc[ct][2] + bv0, cacc[ct][3] + bv1);
            }
        }
        if (more) cp_wait0();
        __syncthreads();
    }
}

// ---------------------------------------------------------------------------
// mma.sync flash attention (no-rescale online softmax), cp.async K/V staging.
// ---------------------------------------------------------------------------
#define QS_OFF 0
#define QROW   272
#define KS_OFF 34816
#define KROWB  272
#define KBUF   17408               // 64 rows * 272
#define VS_OFF 69632
#define VROWT  272
#define VBUF   17408               // 64 rows * 272
#define SM_TOT 104448

__global__ __launch_bounds__(256, 1) void attn_mma_kernel()
{
    extern __shared__ char smem[];
    const uint32_t sb  = smem_u32(smem);
    const int tid  = threadIdx.x;
    const int lane = tid & 31;
    const int wid  = tid >> 5;
    const int b    = blockIdx.y;
    const int i0   = blockIdx.x * 128;
    const int iw   = wid * 16;

    const __nv_bfloat16* qg = d_tT + ((size_t)b * N_ + i0) * CI_;
    const __nv_bfloat16* kp = d_pT + (size_t)b * N_ * CI_;
    const __nv_bfloat16* gp = d_gT + (size_t)b * N_ * CI_;

    // ---- prologue via cp.async: Q (2048 granules), K0/V0 (1024 each) ----
    #pragma unroll
    for (int it = 0; it < 8; it++) {
        int g = tid + it * 256;
        int row = g >> 4, c8 = g & 15;
        cp_async16(sb + QS_OFF + row * QROW + c8 * 16,
                   qg + (size_t)row * CI_ + c8 * 8);
    }
    #pragma unroll
    for (int it = 0; it < 4; it++) {
        int g = tid + it * 256;
        int row = g >> 4, c8 = g & 15;
        cp_async16(sb + KS_OFF + row * KROWB + c8 * 16,
                   kp + (size_t)row * CI_ + c8 * 8);
        cp_async16(sb + VS_OFF + row * VROWT + c8 * 16,
                   gp + (size_t)row * CI_ + c8 * 8);
    }
    cp_commit();
    cp_wait0();
    __syncthreads();

    // ---- Q fragments, held in registers for the whole kernel ----
    uint32_t qf[8][4];
    {
        const int sub = lane >> 3, r = lane & 7;
        const int qrow = iw + (sub & 1) * 8 + r;
        const int qcol = (sub >> 1) * 8;
        #pragma unroll
        for (int kt = 0; kt < 8; kt++) {
            uint32_t addr = sb + QS_OFF + qrow * QROW + (kt * 16 + qcol) * 2;
            ldsm_x4(addr, qf[kt][0], qf[kt][1], qf[kt][2], qf[kt][3]);
        }
    }

    float yacc[16][4];
    #pragma unroll
    for (int ct = 0; ct < 16; ct++)
        #pragma unroll
        for (int q = 0; q < 4; q++) yacc[ct][q] = 0.f;
    float l0 = 0.f, l1 = 0.f;

    const int lr  = lane & 7;
    const int ls8 = (lane >> 3) * 8;

    for (int n = 0; n < NCH; n++) {
        // async-stage next chunk into the other buffers
        const bool more = (n + 1 < NCH);
        if (more) {
            const size_t jb = (size_t)(n + 1) * 64;
            const uint32_t kdst = sb + KS_OFF + (uint32_t)((n + 1) & 1) * KBUF;
            const uint32_t vdst = sb + VS_OFF + (uint32_t)((n + 1) & 1) * VBUF;
            #pragma unroll
            for (int it = 0; it < 4; it++) {
                int g = tid + it * 256;
                int row = g >> 4, c8 = g & 15;
                cp_async16(kdst + row * KROWB + c8 * 16,
                           kp + (jb + row) * CI_ + c8 * 8);
                cp_async16(vdst + row * VROWT + c8 * 16,
                           gp + (jb + row) * CI_ + c8 * 8);
            }
            cp_commit();
        }

        const uint32_t kb = sb + KS_OFF + (uint32_t)(n & 1) * KBUF;
        const uint32_t vb = sb + VS_OFF + (uint32_t)(n & 1) * VBUF;

        // ---- S = Q K^T  (128 x 64, K=128) ----
        float sacc[8][4];
        #pragma unroll
        for (int jt = 0; jt < 8; jt++)
            #pragma unroll
            for (int q = 0; q < 4; q++) sacc[jt][q] = 0.f;

        #pragma unroll
        for (int jt = 0; jt < 8; jt++) {
            uint32_t rowaddr = kb + (jt * 8 + lr) * KROWB + ls8 * 2;
            #pragma unroll
            for (int kt2 = 0; kt2 < 4; kt2++) {
                uint32_t b0, b1, b2, b3;
                ldsm_x4(rowaddr + kt2 * 64, b0, b1, b2, b3);
                mma_bf16(sacc[jt], qf[2 * kt2],     b0, b1);
                mma_bf16(sacc[jt], qf[2 * kt2 + 1], b2, b3);
            }
        }

        // ---- exp + row-sum; repack C frags as A frags for P·V ----
        uint32_t pa[4][4];
        #pragma unroll
        for (int st = 0; st < 8; st++) {
            float e0 = __expf(sacc[st][0]);
            float e1 = __expf(sacc[st][1]);
            float e2 = __expf(sacc[st][2]);
            float e3 = __expf(sacc[st][3]);
            l0 += e0 + e1;
            l1 += e2 + e3;
            pa[st >> 1][(st & 1) * 2 + 0] = pack_bf16(e0, e1);
            pa[st >> 1][(st & 1) * 2 + 1] = pack_bf16(e2, e3);
        }

        // ---- Y += P V^T, V^T via trans-ldmatrix from [j][c] chunk ----
        #pragma unroll
        for (int ct = 0; ct < 16; ct++) {
            uint32_t base = vb + ((lane >> 3) * 8 + (lane & 7)) * VROWT + ct * 16;
            #pragma unroll
            for (int j2 = 0; j2 < 2; j2++) {
                uint32_t b0, b1, b2, b3;
                ldsm_x4_t(base + j2 * 32 * VROWT, b0, b1, b2, b3);
                mma_bf16(yacc[ct], pa[2 * j2],     b0, b1);
                mma_bf16(yacc[ct], pa[2 * j2 + 1], b2, b3);
            }
        }

        if (more) cp_wait0();
        __syncthreads();
    }

    // ---- finalize: quad-reduce row sums, normalize, store bf16 ----
    l0 += __shfl_xor_sync(0xffffffffu, l0, 1);
    l0 += __shfl_xor_sync(0xffffffffu, l0, 2);
    l1 += __shfl_xor_sync(0xffffffffu, l1, 1);
    l1 += __shfl_xor_sync(0xffffffffu, l1, 2);
    const float r0 = 1.f / l0;
    const float r1 = 1.f / l1;

    const int row0 = i0 + iw + (lane >> 2);
    uint32_t* y0 = (uint32_t*)(d_yT + ((size_t)b * N_ + row0)     * CI_ + 2 * (lane & 3));
    uint32_t* y1 = (uint32_t*)(d_yT + ((size_t)b * N_ + row0 + 8) * CI_ + 2 * (lane & 3));
    #pragma unroll
    for (int ct = 0; ct < 16; ct++) {
        y0[ct * 4] = pack_bf16(yacc[ct][0] * r0, yacc[ct][1] * r0);
        y1[ct * 4] = pack_bf16(yacc[ct][2] * r1, yacc[ct][3] * r1);
    }
}

// ---------------------------------------------------------------------------
// out_tc: out[o][n] = sum_ci Wo[o][ci]*yT[n][ci] + bo[o] + x[o][n]
// Wo bf16 via cp.async; x residuals prefetched distance-2; 2 CTAs/SM.
// ---------------------------------------------------------------------------
#define OW_OFF 0                   // Wo tile: 128 o-rows x 272B
#define OWROW  272
#define OY_OFF 34816               // yT tile: 128 n-rows x 272B
#define OYROW  272
#define O_SMEM 69632

__global__ __launch_bounds__(256, 2) void out_tc_kernel(
    const float* __restrict__ x,
    const float* __restrict__ bo,
    float* __restrict__ out)
{
    extern __shared__ char smem[];
    const uint32_t sb = smem_u32(smem);
    const int tid  = threadIdx.x;
    const int lane = tid & 31;
    const int wid  = tid >> 5;
    const int b    = blockIdx.z;
    const int o0   = blockIdx.y * 128;
    const int n0   = blockIdx.x * 128;
    const int iw   = wid * 16;
    const int lr   = lane & 7;
    const int ls8  = (lane >> 3) * 8;

    // Wo + yT tiles via cp.async (both bf16)
    #pragma unroll
    for (int it = 0; it < 8; it++) {
        int g = tid + it * 256;
        int row = g >> 4, c8 = g & 15;
        cp_async16(sb + OW_OFF + row * OWROW + c8 * 16,
                   d_Wob + (size_t)(o0 + row) * CI_ + c8 * 8);
        cp_async16(sb + OY_OFF + row * OYROW + c8 * 16,
                   d_yT + ((size_t)b * N_ + n0 + row) * CI_ + c8 * 8);
    }
    cp_commit();
    cp_wait0();
    __syncthreads();

    // A fragments (Wo, 16 o-rows per warp, K=128)
    uint32_t af[8][4];
    {
        const int sub = lane >> 3, r = lane & 7;
        const int arow = iw + (sub & 1) * 8 + r;
        const int acol = (sub >> 1) * 8;
        #pragma unroll
        for (int kt = 0; kt < 8; kt++) {
            uint32_t addr = sb + OW_OFF + arow * OWROW + (kt * 16 + acol) * 2;
            ldsm_x4(addr, af[kt][0], af[kt][1], af[kt][2], af[kt][3]);
        }
    }

    const int orow = o0 + iw + (lane >> 2);
    const float bv0 = bo[orow];
    const float bv1 = bo[orow + 8];
    const size_t base0 = ((size_t)b * C_ + orow)     * N_ + n0 + 2 * (lane & 3);
    const size_t base1 = ((size_t)b * C_ + orow + 8) * N_ + n0 + 2 * (lane & 3);

    // residual ring buffer, prefetch distance 2
    float2 xr[2][2];
    xr[0][0] = *(const float2*)&x[base0];
    xr[0][1] = *(const float2*)&x[base1];
    xr[1][0] = *(const float2*)&x[base0 + 8];
    xr[1][1] = *(const float2*)&x[base1 + 8];

    #pragma unroll
    for (int nt = 0; nt < 16; nt++) {
        float2 nx0, nx1;
        if (nt + 2 < 16) {
            nx0 = *(const float2*)&x[base0 + (nt + 2) * 8];
            nx1 = *(const float2*)&x[base1 + (nt + 2) * 8];
        }
        float acc[4] = {0.f, 0.f, 0.f, 0.f};
        uint32_t rowaddr = sb + OY_OFF + (nt * 8 + lr) * OYROW + ls8 * 2;
        #pragma unroll
        for (int kt2 = 0; kt2 < 4; kt2++) {
            uint32_t b0, b1, b2, b3;
            ldsm_x4(rowaddr + kt2 * 64, b0, b1, b2, b3);
            mma_bf16(acc, af[2 * kt2],     b0, b1);
            mma_bf16(acc, af[2 * kt2 + 1], b2, b3);
        }
        float2 x0 = xr[nt & 1][0];
        float2 x1 = xr[nt & 1][1];
        *(float2*)&out[base0 + nt * 8] = make_float2(acc[0] + bv0 + x0.x,
                                                     acc[1] + bv0 + x0.y);
        *(float2*)&out[base1 + nt * 8] = make_float2(acc[2] + bv1 + x1.x,
                                                     acc[3] + bv1 + x1.y);
        if (nt + 2 < 16) {
            xr[nt & 1][0] = nx0;
            xr[nt & 1][1] = nx1;
        }
    }
}

// ---------------------------------------------------------------------------
extern "C" void kernel_launch(void* const* d_in, const int* in_sizes, int n_in,
                              void* d_out, int out_size)
{
    const float* x  = (const float*)d_in[0];
    const float* Wg = (const float*)d_in[1];
    const float* bg = (const float*)d_in[2];
    const float* Wt = (const float*)d_in[3];
    const float* bt = (const float*)d_in[4];
    const float* Wp = (const float*)d_in[5];
    const float* bp = (const float*)d_in[6];
    const float* Wo = (const float*)d_in[7];
    const float* bo = (const float*)d_in[8];
    float* out = (float*)d_out;

    cudaFuncSetAttribute(proj_tc_kernel,
                         cudaFuncAttributeMaxDynamicSharedMemorySize, P_SMEM);
    cudaFuncSetAttribute(attn_mma_kernel,
                         cudaFuncAttributeMaxDynamicSharedMemorySize, SM_TOT);
    cudaFuncSetAttribute(out_tc_kernel,
                         cudaFuncAttributeMaxDynamicSharedMemorySize, O_SMEM);

    wconv_kernel<<<96, 256>>>(Wg, Wt, Wp, Wo);
    proj_tc_kernel<<<dim3(N_ / 64, B_), 256, P_SMEM>>>(x, bg, bt, bp);
    attn_mma_kernel<<<dim3(N_ / 128, B_), 256, SM_TOT>>>();
    out_tc_kernel<<<dim3(N_ / 128, 2, B_), 256, O_SMEM>>>(x, bo, out);
}